// round 3
// baseline (speedup 1.0000x reference)
#include <cuda_runtime.h>
#include <math.h>

// Problem constants (nondecayRNN: B=256, T=512, I=128, H=1024, O=128)
namespace {
constexpr int kB = 256;
constexpr int kT = 512;
constexpr int kI = 128;
constexpr int kH = 1024;
constexpr int kO = 128;

constexpr int kGroups        = 8;               // independent batch groups
constexpr int kBc            = kB / kGroups;    // 32 batch rows per group
constexpr int kTilesPerGroup = 16;              // N-tiles (of 64) covering H=1024
constexpr int kTN            = kH / kTilesPerGroup; // 64
}

// Per-group monotonic barrier counters (reset by init kernel each launch).
__device__ unsigned int g_count[kGroups];

__global__ void init_counters_kernel() {
    if (threadIdx.x < kGroups) g_count[threadIdx.x] = 0u;
}

// ---------------------------------------------------------------------------
// Persistent recurrence kernel.
// Grid: 128 CTAs = 8 groups x 16 N-tiles. Block: 128 threads.
// Each CTA computes a 32(batch) x 64(H) tile of h_t for all t:
//   h_t = relu( b_in + x_t @ W_in^T + h_{t-1} @ Wrec^T )
// implemented as a K=1152 GEMM (1024 from h_{t-1}/Wrec + 128 from x_t/W_in).
// h_{t-1} is read straight from the hiddens output buffer; a 16-CTA group
// barrier (atomic counter in L2) separates steps.
// ---------------------------------------------------------------------------
__global__ __launch_bounds__(128, 1)
void rnn_recurrence_kernel(const float* __restrict__ x,
                           const float* __restrict__ W_in,
                           const float* __restrict__ b_in,
                           const float* __restrict__ Wrec,
                           float* __restrict__ hid)   // [B, T, H] output
{
    __shared__ __align__(16) float As[32][36];   // k-major h/x tile (padded)
    __shared__ __align__(16) float Bs[32][68];   // k-major W tile  (padded)

    const int tid = threadIdx.x;
    const int g   = blockIdx.x / kTilesPerGroup;
    const int jt  = blockIdx.x % kTilesPerGroup;
    const int j0  = jt * kTN;        // H-column offset of this tile
    const int b0  = g * kBc;         // batch-row offset of this group
    const int ty  = tid >> 4;        // 0..7  -> rows 4*ty..4*ty+3
    const int tx  = tid & 15;        // 0..15 -> cols 4*tx..4*tx+3

    float bias[4];
#pragma unroll
    for (int c = 0; c < 4; ++c) bias[c] = b_in[j0 + 4 * tx + c];

    const size_t strideH = (size_t)kT * kH;  // batch-row stride in hid
    const size_t strideX = (size_t)kT * kI;  // batch-row stride in x

    for (int t = 0; t < kT; ++t) {
        float acc[4][4];
#pragma unroll
        for (int i = 0; i < 4; ++i)
#pragma unroll
            for (int c = 0; c < 4; ++c) acc[i][c] = bias[c];

        // k-tiles 0..31: h_{t-1} @ Wrec^T  (skipped at t==0, h_{-1}=0)
        // k-tiles 32..35: x_t @ W_in^T
        const int kt_begin = (t == 0) ? 32 : 0;
#pragma unroll 1
        for (int kt = kt_begin; kt < 36; ++kt) {
            const float* Abase;
            const float* Bbase;
            size_t sA;
            int sB;
            if (kt < 32) {
                const int k0 = kt * 32;
                Abase = hid + (size_t)b0 * strideH + (size_t)(t - 1) * kH + k0;
                sA = strideH;
                Bbase = Wrec + (size_t)j0 * kH + k0;
                sB = kH;
            } else {
                const int k0 = (kt - 32) * 32;
                Abase = x + (size_t)b0 * strideX + (size_t)t * kI + k0;
                sA = strideX;
                Bbase = W_in + (size_t)j0 * kI + k0;
                sB = kI;
            }

            __syncthreads();
            // Stage A tile: 32 rows x 32 k, transposed into As[k][row]
#pragma unroll
            for (int q = 0; q < 2; ++q) {
                int slot = tid + q * 128;
                int row  = slot >> 3;
                int kk4  = (slot & 7) * 4;
                float4 v = *reinterpret_cast<const float4*>(
                    Abase + (size_t)row * sA + kk4);
                As[kk4 + 0][row] = v.x;
                As[kk4 + 1][row] = v.y;
                As[kk4 + 2][row] = v.z;
                As[kk4 + 3][row] = v.w;
            }
            // Stage B tile: 64 j x 32 k, transposed into Bs[k][j]
#pragma unroll
            for (int q = 0; q < 4; ++q) {
                int slot = tid + q * 128;
                int j    = slot >> 3;
                int kk4  = (slot & 7) * 4;
                float4 v = *reinterpret_cast<const float4*>(
                    Bbase + (size_t)j * sB + kk4);
                Bs[kk4 + 0][j] = v.x;
                Bs[kk4 + 1][j] = v.y;
                Bs[kk4 + 2][j] = v.z;
                Bs[kk4 + 3][j] = v.w;
            }
            __syncthreads();

#pragma unroll
            for (int kk = 0; kk < 32; ++kk) {
                float4 a = *reinterpret_cast<const float4*>(&As[kk][4 * ty]);
                float4 b = *reinterpret_cast<const float4*>(&Bs[kk][4 * tx]);
                float av[4] = {a.x, a.y, a.z, a.w};
                float bv[4] = {b.x, b.y, b.z, b.w};
#pragma unroll
                for (int i = 0; i < 4; ++i)
#pragma unroll
                    for (int c = 0; c < 4; ++c)
                        acc[i][c] = fmaf(av[i], bv[c], acc[i][c]);
            }
        }

        // ReLU + store this step's hidden tile directly into the output buffer
        float* hbase = hid + (size_t)b0 * strideH + (size_t)t * kH + j0;
#pragma unroll
        for (int i = 0; i < 4; ++i) {
            float4 v;
            v.x = fmaxf(acc[i][0], 0.0f);
            v.y = fmaxf(acc[i][1], 0.0f);
            v.z = fmaxf(acc[i][2], 0.0f);
            v.w = fmaxf(acc[i][3], 0.0f);
            *reinterpret_cast<float4*>(
                hbase + (size_t)(4 * ty + i) * strideH + 4 * tx) = v;
        }

        // ---- group barrier: all 16 CTAs of group g finished step t ----
        __threadfence();     // make h_t stores visible device-wide
        __syncthreads();     // all threads in CTA fenced
        if (tid == 0) {
            atomicAdd(&g_count[g], 1u);
            const unsigned int target =
                (unsigned int)(kTilesPerGroup * (t + 1));
            while (atomicAdd(&g_count[g], 0u) < target) { /* spin in L2 */ }
        }
        __syncthreads();     // release whole CTA into step t+1
    }
}

// ---------------------------------------------------------------------------
// Output projection + softmax over all B*T rows:
//   outs[row] = softmax( hid[row] @ W_out^T + b_out )
// Grid: 2048 CTAs (64 rows each). Block: 256 threads; thread = 4 rows x 8 cols.
// ---------------------------------------------------------------------------
__global__ __launch_bounds__(256, 1)
void rnn_output_kernel(const float* __restrict__ hid,
                       const float* __restrict__ W_out,
                       const float* __restrict__ b_out,
                       float* __restrict__ outs)
{
    __shared__ __align__(16) float Hs[32][68];    // h tile   [k][row]
    __shared__ __align__(16) float Ws[32][132];   // W_out    [k][o]

    const int tid = threadIdx.x;
    const int ty  = tid >> 4;    // 0..15 -> rows 4*ty..4*ty+3
    const int tx  = tid & 15;    // 0..15 -> cols 8*tx..8*tx+7
    const size_t r0 = (size_t)blockIdx.x * 64;

    float bias[8];
#pragma unroll
    for (int c = 0; c < 8; ++c) bias[c] = b_out[8 * tx + c];

    float acc[4][8];
#pragma unroll
    for (int i = 0; i < 4; ++i)
#pragma unroll
        for (int c = 0; c < 8; ++c) acc[i][c] = bias[c];

#pragma unroll 1
    for (int kt = 0; kt < 32; ++kt) {
        const int k0 = kt * 32;
        __syncthreads();
        // stage 64 rows x 32 k of hiddens
#pragma unroll
        for (int q = 0; q < 2; ++q) {
            int slot = tid + q * 256;
            int row  = slot >> 3;
            int kk4  = (slot & 7) * 4;
            float4 v = *reinterpret_cast<const float4*>(
                hid + (r0 + row) * kH + k0 + kk4);
            Hs[kk4 + 0][row] = v.x;
            Hs[kk4 + 1][row] = v.y;
            Hs[kk4 + 2][row] = v.z;
            Hs[kk4 + 3][row] = v.w;
        }
        // stage 128 o x 32 k of W_out
#pragma unroll
        for (int q = 0; q < 4; ++q) {
            int slot = tid + q * 256;
            int o    = slot >> 3;
            int kk4  = (slot & 7) * 4;
            float4 v = *reinterpret_cast<const float4*>(
                W_out + (size_t)o * kH + k0 + kk4);
            Ws[kk4 + 0][o] = v.x;
            Ws[kk4 + 1][o] = v.y;
            Ws[kk4 + 2][o] = v.z;
            Ws[kk4 + 3][o] = v.w;
        }
        __syncthreads();

#pragma unroll
        for (int kk = 0; kk < 32; ++kk) {
            float4 a  = *reinterpret_cast<const float4*>(&Hs[kk][4 * ty]);
            float4 w0 = *reinterpret_cast<const float4*>(&Ws[kk][8 * tx]);
            float4 w1 = *reinterpret_cast<const float4*>(&Ws[kk][8 * tx + 4]);
            float av[4] = {a.x, a.y, a.z, a.w};
            float wv[8] = {w0.x, w0.y, w0.z, w0.w, w1.x, w1.y, w1.z, w1.w};
#pragma unroll
            for (int i = 0; i < 4; ++i)
#pragma unroll
                for (int c = 0; c < 8; ++c)
                    acc[i][c] = fmaf(av[i], wv[c], acc[i][c]);
        }
    }

    // softmax per row: each row's 128 logits live in a 16-lane half-warp
    // (8 per lane) -> butterfly reductions with width=16.
#pragma unroll
    for (int i = 0; i < 4; ++i) {
        float m = acc[i][0];
#pragma unroll
        for (int c = 1; c < 8; ++c) m = fmaxf(m, acc[i][c]);
#pragma unroll
        for (int d = 8; d >= 1; d >>= 1)
            m = fmaxf(m, __shfl_xor_sync(0xffffffffu, m, d, 16));

        float e[8];
        float s = 0.0f;
#pragma unroll
        for (int c = 0; c < 8; ++c) {
            e[c] = expf(acc[i][c] - m);
            s += e[c];
        }
#pragma unroll
        for (int d = 8; d >= 1; d >>= 1)
            s += __shfl_xor_sync(0xffffffffu, s, d, 16);

        const float inv = 1.0f / s;
        const size_t row = r0 + 4 * ty + i;
        float4 o0, o1;
        o0.x = e[0] * inv; o0.y = e[1] * inv; o0.z = e[2] * inv; o0.w = e[3] * inv;
        o1.x = e[4] * inv; o1.y = e[5] * inv; o1.z = e[6] * inv; o1.w = e[7] * inv;
        *reinterpret_cast<float4*>(outs + row * kO + 8 * tx)     = o0;
        *reinterpret_cast<float4*>(outs + row * kO + 8 * tx + 4) = o1;
    }
}

// ---------------------------------------------------------------------------
// d_in order (metadata): x, W_in, b_in, Wrec, W_out, b_out
// d_out: hiddens [B,T,H] (fp32) followed by outs [B,T,O] (fp32)
// ---------------------------------------------------------------------------
extern "C" void kernel_launch(void* const* d_in, const int* in_sizes, int n_in,
                              void* d_out, int out_size) {
    (void)in_sizes; (void)n_in; (void)out_size;
    const float* x     = (const float*)d_in[0];
    const float* W_in  = (const float*)d_in[1];
    const float* b_in  = (const float*)d_in[2];
    const float* Wrec  = (const float*)d_in[3];
    const float* W_out = (const float*)d_in[4];
    const float* b_out = (const float*)d_in[5];

    float* hid  = (float*)d_out;                        // [B,T,H]
    float* outs = hid + (size_t)kB * kT * kH;           // [B,T,O]

    init_counters_kernel<<<1, 32>>>();
    rnn_recurrence_kernel<<<kGroups * kTilesPerGroup, 128>>>(
        x, W_in, b_in, Wrec, hid);
    rnn_output_kernel<<<(kB * kT) / 64, 256>>>(hid, W_out, b_out, outs);
}

// round 4
// speedup vs baseline: 1.0000x; 1.0000x over previous
#include <cuda_runtime.h>
#include <math.h>

// Problem constants (nondecayRNN: B=256, T=512, I=128, H=1024, O=128)
namespace {
constexpr int kB = 256;
constexpr int kT = 512;
constexpr int kI = 128;
constexpr int kH = 1024;
constexpr int kO = 128;

constexpr int kGroups        = 8;               // independent batch groups
constexpr int kBc            = kB / kGroups;    // 32 batch rows per group
constexpr int kTilesPerGroup = 16;              // N-tiles (of 64) covering H=1024
constexpr int kTN            = kH / kTilesPerGroup; // 64
}

// Per-group monotonic barrier counters (reset by init kernel each launch).
__device__ unsigned int g_count[kGroups];

__global__ void init_counters_kernel() {
    if (threadIdx.x < kGroups) g_count[threadIdx.x] = 0u;
}

// ---------------------------------------------------------------------------
// Persistent recurrence kernel.
// Grid: 128 CTAs = 8 groups x 16 N-tiles. Block: 128 threads.
// Each CTA computes a 32(batch) x 64(H) tile of h_t for all t:
//   h_t = relu( b_in + x_t @ W_in^T + h_{t-1} @ Wrec^T )
// implemented as a K=1152 GEMM (1024 from h_{t-1}/Wrec + 128 from x_t/W_in).
// h_{t-1} is read straight from the hiddens output buffer; a 16-CTA group
// barrier (atomic counter in L2) separates steps.
// ---------------------------------------------------------------------------
__global__ __launch_bounds__(128, 1)
void rnn_recurrence_kernel(const float* __restrict__ x,
                           const float* __restrict__ W_in,
                           const float* __restrict__ b_in,
                           const float* __restrict__ Wrec,
                           float* __restrict__ hid)   // [B, T, H] output
{
    __shared__ __align__(16) float As[32][36];   // k-major h/x tile (padded)
    __shared__ __align__(16) float Bs[32][68];   // k-major W tile  (padded)

    const int tid = threadIdx.x;
    const int g   = blockIdx.x / kTilesPerGroup;
    const int jt  = blockIdx.x % kTilesPerGroup;
    const int j0  = jt * kTN;        // H-column offset of this tile
    const int b0  = g * kBc;         // batch-row offset of this group
    const int ty  = tid >> 4;        // 0..7  -> rows 4*ty..4*ty+3
    const int tx  = tid & 15;        // 0..15 -> cols 4*tx..4*tx+3

    float bias[4];
#pragma unroll
    for (int c = 0; c < 4; ++c) bias[c] = b_in[j0 + 4 * tx + c];

    const size_t strideH = (size_t)kT * kH;  // batch-row stride in hid
    const size_t strideX = (size_t)kT * kI;  // batch-row stride in x

    for (int t = 0; t < kT; ++t) {
        float acc[4][4];
#pragma unroll
        for (int i = 0; i < 4; ++i)
#pragma unroll
            for (int c = 0; c < 4; ++c) acc[i][c] = bias[c];

        // k-tiles 0..31: h_{t-1} @ Wrec^T  (skipped at t==0, h_{-1}=0)
        // k-tiles 32..35: x_t @ W_in^T
        const int kt_begin = (t == 0) ? 32 : 0;
#pragma unroll 1
        for (int kt = kt_begin; kt < 36; ++kt) {
            const float* Abase;
            const float* Bbase;
            size_t sA;
            int sB;
            if (kt < 32) {
                const int k0 = kt * 32;
                Abase = hid + (size_t)b0 * strideH + (size_t)(t - 1) * kH + k0;
                sA = strideH;
                Bbase = Wrec + (size_t)j0 * kH + k0;
                sB = kH;
            } else {
                const int k0 = (kt - 32) * 32;
                Abase = x + (size_t)b0 * strideX + (size_t)t * kI + k0;
                sA = strideX;
                Bbase = W_in + (size_t)j0 * kI + k0;
                sB = kI;
            }

            __syncthreads();
            // Stage A tile: 32 rows x 32 k, transposed into As[k][row]
#pragma unroll
            for (int q = 0; q < 2; ++q) {
                int slot = tid + q * 128;
                int row  = slot >> 3;
                int kk4  = (slot & 7) * 4;
                float4 v = *reinterpret_cast<const float4*>(
                    Abase + (size_t)row * sA + kk4);
                As[kk4 + 0][row] = v.x;
                As[kk4 + 1][row] = v.y;
                As[kk4 + 2][row] = v.z;
                As[kk4 + 3][row] = v.w;
            }
            // Stage B tile: 64 j x 32 k, transposed into Bs[k][j]
#pragma unroll
            for (int q = 0; q < 4; ++q) {
                int slot = tid + q * 128;
                int j    = slot >> 3;
                int kk4  = (slot & 7) * 4;
                float4 v = *reinterpret_cast<const float4*>(
                    Bbase + (size_t)j * sB + kk4);
                Bs[kk4 + 0][j] = v.x;
                Bs[kk4 + 1][j] = v.y;
                Bs[kk4 + 2][j] = v.z;
                Bs[kk4 + 3][j] = v.w;
            }
            __syncthreads();

#pragma unroll
            for (int kk = 0; kk < 32; ++kk) {
                float4 a = *reinterpret_cast<const float4*>(&As[kk][4 * ty]);
                float4 b = *reinterpret_cast<const float4*>(&Bs[kk][4 * tx]);
                float av[4] = {a.x, a.y, a.z, a.w};
                float bv[4] = {b.x, b.y, b.z, b.w};
#pragma unroll
                for (int i = 0; i < 4; ++i)
#pragma unroll
                    for (int c = 0; c < 4; ++c)
                        acc[i][c] = fmaf(av[i], bv[c], acc[i][c]);
            }
        }

        // ReLU + store this step's hidden tile directly into the output buffer
        float* hbase = hid + (size_t)b0 * strideH + (size_t)t * kH + j0;
#pragma unroll
        for (int i = 0; i < 4; ++i) {
            float4 v;
            v.x = fmaxf(acc[i][0], 0.0f);
            v.y = fmaxf(acc[i][1], 0.0f);
            v.z = fmaxf(acc[i][2], 0.0f);
            v.w = fmaxf(acc[i][3], 0.0f);
            *reinterpret_cast<float4*>(
                hbase + (size_t)(4 * ty + i) * strideH + 4 * tx) = v;
        }

        // ---- group barrier: all 16 CTAs of group g finished step t ----
        __threadfence();     // make h_t stores visible device-wide
        __syncthreads();     // all threads in CTA fenced
        if (tid == 0) {
            atomicAdd(&g_count[g], 1u);
            const unsigned int target =
                (unsigned int)(kTilesPerGroup * (t + 1));
            while (atomicAdd(&g_count[g], 0u) < target) { /* spin in L2 */ }
        }
        __syncthreads();     // release whole CTA into step t+1
    }
}

// ---------------------------------------------------------------------------
// Output projection + softmax over all B*T rows:
//   outs[row] = softmax( hid[row] @ W_out^T + b_out )
// Grid: 2048 CTAs (64 rows each). Block: 256 threads; thread = 4 rows x 8 cols.
// ---------------------------------------------------------------------------
__global__ __launch_bounds__(256, 1)
void rnn_output_kernel(const float* __restrict__ hid,
                       const float* __restrict__ W_out,
                       const float* __restrict__ b_out,
                       float* __restrict__ outs)
{
    __shared__ __align__(16) float Hs[32][68];    // h tile   [k][row]
    __shared__ __align__(16) float Ws[32][132];   // W_out    [k][o]

    const int tid = threadIdx.x;
    const int ty  = tid >> 4;    // 0..15 -> rows 4*ty..4*ty+3
    const int tx  = tid & 15;    // 0..15 -> cols 8*tx..8*tx+7
    const size_t r0 = (size_t)blockIdx.x * 64;

    float bias[8];
#pragma unroll
    for (int c = 0; c < 8; ++c) bias[c] = b_out[8 * tx + c];

    float acc[4][8];
#pragma unroll
    for (int i = 0; i < 4; ++i)
#pragma unroll
        for (int c = 0; c < 8; ++c) acc[i][c] = bias[c];

#pragma unroll 1
    for (int kt = 0; kt < 32; ++kt) {
        const int k0 = kt * 32;
        __syncthreads();
        // stage 64 rows x 32 k of hiddens
#pragma unroll
        for (int q = 0; q < 2; ++q) {
            int slot = tid + q * 256;
            int row  = slot >> 3;
            int kk4  = (slot & 7) * 4;
            float4 v = *reinterpret_cast<const float4*>(
                hid + (r0 + row) * kH + k0 + kk4);
            Hs[kk4 + 0][row] = v.x;
            Hs[kk4 + 1][row] = v.y;
            Hs[kk4 + 2][row] = v.z;
            Hs[kk4 + 3][row] = v.w;
        }
        // stage 128 o x 32 k of W_out
#pragma unroll
        for (int q = 0; q < 4; ++q) {
            int slot = tid + q * 256;
            int o    = slot >> 3;
            int kk4  = (slot & 7) * 4;
            float4 v = *reinterpret_cast<const float4*>(
                W_out + (size_t)o * kH + k0 + kk4);
            Ws[kk4 + 0][o] = v.x;
            Ws[kk4 + 1][o] = v.y;
            Ws[kk4 + 2][o] = v.z;
            Ws[kk4 + 3][o] = v.w;
        }
        __syncthreads();

#pragma unroll
        for (int kk = 0; kk < 32; ++kk) {
            float4 a  = *reinterpret_cast<const float4*>(&Hs[kk][4 * ty]);
            float4 w0 = *reinterpret_cast<const float4*>(&Ws[kk][8 * tx]);
            float4 w1 = *reinterpret_cast<const float4*>(&Ws[kk][8 * tx + 4]);
            float av[4] = {a.x, a.y, a.z, a.w};
            float wv[8] = {w0.x, w0.y, w0.z, w0.w, w1.x, w1.y, w1.z, w1.w};
#pragma unroll
            for (int i = 0; i < 4; ++i)
#pragma unroll
                for (int c = 0; c < 8; ++c)
                    acc[i][c] = fmaf(av[i], wv[c], acc[i][c]);
        }
    }

    // softmax per row: each row's 128 logits live in a 16-lane half-warp
    // (8 per lane) -> butterfly reductions with width=16.
#pragma unroll
    for (int i = 0; i < 4; ++i) {
        float m = acc[i][0];
#pragma unroll
        for (int c = 1; c < 8; ++c) m = fmaxf(m, acc[i][c]);
#pragma unroll
        for (int d = 8; d >= 1; d >>= 1)
            m = fmaxf(m, __shfl_xor_sync(0xffffffffu, m, d, 16));

        float e[8];
        float s = 0.0f;
#pragma unroll
        for (int c = 0; c < 8; ++c) {
            e[c] = expf(acc[i][c] - m);
            s += e[c];
        }
#pragma unroll
        for (int d = 8; d >= 1; d >>= 1)
            s += __shfl_xor_sync(0xffffffffu, s, d, 16);

        const float inv = 1.0f / s;
        const size_t row = r0 + 4 * ty + i;
        float4 o0, o1;
        o0.x = e[0] * inv; o0.y = e[1] * inv; o0.z = e[2] * inv; o0.w = e[3] * inv;
        o1.x = e[4] * inv; o1.y = e[5] * inv; o1.z = e[6] * inv; o1.w = e[7] * inv;
        *reinterpret_cast<float4*>(outs + row * kO + 8 * tx)     = o0;
        *reinterpret_cast<float4*>(outs + row * kO + 8 * tx + 4) = o1;
    }
}

// ---------------------------------------------------------------------------
// d_in order (metadata): x, W_in, b_in, Wrec, W_out, b_out
// d_out: hiddens [B,T,H] (fp32) followed by outs [B,T,O] (fp32)
// ---------------------------------------------------------------------------
extern "C" void kernel_launch(void* const* d_in, const int* in_sizes, int n_in,
                              void* d_out, int out_size) {
    (void)in_sizes; (void)n_in; (void)out_size;
    const float* x     = (const float*)d_in[0];
    const float* W_in  = (const float*)d_in[1];
    const float* b_in  = (const float*)d_in[2];
    const float* Wrec  = (const float*)d_in[3];
    const float* W_out = (const float*)d_in[4];
    const float* b_out = (const float*)d_in[5];

    float* hid  = (float*)d_out;                        // [B,T,H]
    float* outs = hid + (size_t)kB * kT * kH;           // [B,T,O]

    init_counters_kernel<<<1, 32>>>();
    rnn_recurrence_kernel<<<kGroups * kTilesPerGroup, 128>>>(
        x, W_in, b_in, Wrec, hid);
    rnn_output_kernel<<<(kB * kT) / 64, 256>>>(hid, W_out, b_out, outs);
}

// round 5
// speedup vs baseline: 2.7023x; 2.7023x over previous
#include <cuda_runtime.h>
#include <cuda_bf16.h>
#include <math.h>
#include <stdint.h>

// Problem constants (nondecayRNN: B=256, T=512, I=128, H=1024, O=128)
namespace {
constexpr int kB = 256;
constexpr int kT = 512;
constexpr int kI = 128;
constexpr int kH = 1024;
constexpr int kO = 128;

constexpr int kGroups        = 8;                 // independent batch groups
constexpr int kBc            = kB / kGroups;      // 32 batch rows / group
constexpr int kTilesPerGroup = 16;                // N-tiles of 64 over H
constexpr int kTN            = kH / kTilesPerGroup; // 64

constexpr int kK      = kH + kI;   // fused K = 1152 (h | x)
constexpr int kChunk  = 128;       // K chunk per stage
// chunks 0..7 come from h (K=1024), chunk 8 from x (K=128)

// SMEM layout (bytes)
constexpr int SBHI_STRIDE = 1160;  // bf16 elems per n-row, padded (1152+8)
constexpr int SCH_STRIDE  = 136;   // bf16 elems per row in chunk bufs (128+8)
constexpr int A_BYTES   = 32 * SCH_STRIDE * 2;        // 8704
constexpr int BLO_BYTES = 64 * SCH_STRIDE * 2;        // 17408
constexpr int BUF_BYTES = 2 * A_BYTES + BLO_BYTES;    // 34816 (Ahi|Alo|Blo)
constexpr int BHI_BYTES = 64 * SBHI_STRIDE * 2;       // 148480 persistent
constexpr int SMEM_TOTAL = BHI_BYTES + 2 * BUF_BYTES; // 218112
}

// ---------------------------------------------------------------------------
// Device scratch (static __device__ arrays — no allocation)
// ---------------------------------------------------------------------------
__device__ unsigned int   g_count[kGroups];                 // group barriers
__device__ __nv_bfloat16  g_W[2][kH * kK];                  // [hi/lo][j*1152+k]
__device__ __nv_bfloat16  g_xs[2][(size_t)kB * kT * kI];    // [hi/lo][(b*T+t)*I+i]
__device__ __nv_bfloat16  g_h[2][2][(size_t)kB * kH];       // [buf][hi/lo][b*H+h]

// ---------------------------------------------------------------------------
// PTX helpers
// ---------------------------------------------------------------------------
__device__ __forceinline__ uint32_t smem_u32(const void* p) {
    return (uint32_t)__cvta_generic_to_shared(p);
}
__device__ __forceinline__ void cpa16(uint32_t dst, const void* src) {
    asm volatile("cp.async.cg.shared.global [%0], [%1], 16;"
                 :: "r"(dst), "l"(src) : "memory");
}
__device__ __forceinline__ void cp_commit() {
    asm volatile("cp.async.commit_group;" ::: "memory");
}
__device__ __forceinline__ void cp_wait0() {
    asm volatile("cp.async.wait_group 0;" ::: "memory");
}
__device__ __forceinline__ void cp_wait1() {
    asm volatile("cp.async.wait_group 1;" ::: "memory");
}
__device__ __forceinline__ void ldm4(uint32_t* r, uint32_t addr) {
    asm volatile("ldmatrix.sync.aligned.m8n8.x4.shared.b16 {%0,%1,%2,%3}, [%4];"
                 : "=r"(r[0]), "=r"(r[1]), "=r"(r[2]), "=r"(r[3]) : "r"(addr));
}
__device__ __forceinline__ void mma16816(float* d, const uint32_t* a,
                                         uint32_t b0, uint32_t b1) {
    asm volatile(
        "mma.sync.aligned.m16n8k16.row.col.f32.bf16.bf16.f32 "
        "{%0,%1,%2,%3}, {%4,%5,%6,%7}, {%8,%9}, {%0,%1,%2,%3};"
        : "+f"(d[0]), "+f"(d[1]), "+f"(d[2]), "+f"(d[3])
        : "r"(a[0]), "r"(a[1]), "r"(a[2]), "r"(a[3]), "r"(b0), "r"(b1));
}
__device__ __forceinline__ void split_bf16(float v, __nv_bfloat16& hi,
                                           __nv_bfloat16& lo) {
    hi = __float2bfloat16(v);
    lo = __float2bfloat16(v - __bfloat162float(hi));
}

// ---------------------------------------------------------------------------
// Prepass: split weights (Wrec|W_in concatenated along K) into bf16 hi/lo
// planes; also reset barrier counters.
// ---------------------------------------------------------------------------
__global__ void convert_w_kernel(const float* __restrict__ Wrec,
                                 const float* __restrict__ W_in) {
    if (blockIdx.x == 0 && threadIdx.x < kGroups) g_count[threadIdx.x] = 0u;
    const int total = kH * kK;
    for (int idx = blockIdx.x * blockDim.x + threadIdx.x; idx < total;
         idx += gridDim.x * blockDim.x) {
        int j = idx / kK, k = idx - j * kK;
        float v = (k < kH) ? Wrec[j * kH + k] : W_in[j * kI + (k - kH)];
        __nv_bfloat16 hi, lo;
        split_bf16(v, hi, lo);
        g_W[0][idx] = hi;
        g_W[1][idx] = lo;
    }
}

// Prepass: split x into bf16 hi/lo planes (same [B][T][I] layout).
__global__ void convert_x_kernel(const float* __restrict__ x) {
    const int n4 = (kB * kT * kI) / 4;
    __nv_bfloat162* xh = reinterpret_cast<__nv_bfloat162*>(g_xs[0]);
    __nv_bfloat162* xl = reinterpret_cast<__nv_bfloat162*>(g_xs[1]);
    for (int i = blockIdx.x * blockDim.x + threadIdx.x; i < n4;
         i += gridDim.x * blockDim.x) {
        float4 v = reinterpret_cast<const float4*>(x)[i];
        float vs[4] = {v.x, v.y, v.z, v.w};
        __nv_bfloat16 hi[4], lo[4];
#pragma unroll
        for (int k = 0; k < 4; ++k) split_bf16(vs[k], hi[k], lo[k]);
        __nv_bfloat162 p;
        p.x = hi[0]; p.y = hi[1]; xh[2 * i]     = p;
        p.x = hi[2]; p.y = hi[3]; xh[2 * i + 1] = p;
        p.x = lo[0]; p.y = lo[1]; xl[2 * i]     = p;
        p.x = lo[2]; p.y = lo[3]; xl[2 * i + 1] = p;
    }
}

// ---------------------------------------------------------------------------
// Tensor-core recurrence. Grid: 128 CTAs = 8 groups x 16 N-tiles.
// Block: 256 threads (8 warps; warp w -> rows 16*(w>>2), cols 16*(w&3)).
// Per CTA per step: 32(batch) x 64(H) output tile, K=1152 fused GEMM with the
// 3-pass bf16 split: D += Ah*Bh + Ah*Bl + Al*Bh. W_hi slice is SMEM-resident;
// W_lo and A(h/x hi+lo) are streamed per 128-wide K chunk via cp.async with
// double buffering.
// ---------------------------------------------------------------------------
__global__ __launch_bounds__(256, 1)
void rnn_rec_tc(const float* __restrict__ b_in,
                float* __restrict__ hid)   // [B, T, H] fp32 output
{
    extern __shared__ char smem[];
    char* sBhi  = smem;                    // persistent W_hi slice [64][1160]
    char* sBuf0 = smem + BHI_BYTES;        // chunk buf 0
    char* sBuf1 = sBuf0 + BUF_BYTES;       // chunk buf 1

    const int tid = threadIdx.x;
    const int g   = blockIdx.x / kTilesPerGroup;
    const int jt  = blockIdx.x % kTilesPerGroup;
    const int j0  = jt * kTN;
    const int b0  = g * kBc;
    const int w   = tid >> 5;
    const int l   = tid & 31;
    const int r0  = (w >> 2) * 16;   // A-row base within 32-row tile
    const int c0  = (w & 3) * 16;    // n base within 64-col tile

    // ---- persistent W_hi slice load (cp.async) ----
#pragma unroll
    for (int j = 0; j < 36; ++j) {                 // 9216 = 64 rows * 144 segs
        int idx = tid + j * 256;
        int row = idx / 144, seg = idx - row * 144;
        uint32_t dst = smem_u32(sBhi + (row * SBHI_STRIDE + seg * 8) * 2);
        cpa16(dst, &g_W[0][(size_t)(j0 + row) * kK + seg * 8]);
    }
    cp_commit();

    // bias per lane: cols nt*8 + 2*(l&3), +1
    float biasv[4];
#pragma unroll
    for (int nt = 0; nt < 2; ++nt) {
        int col = j0 + c0 + nt * 8 + 2 * (l & 3);
        biasv[2 * nt]     = b_in[col];
        biasv[2 * nt + 1] = b_in[col + 1];
    }

    cp_wait0();
    __syncthreads();

    // per-lane ldmatrix offsets
    const int m    = l >> 3;                       // matrix index 0..3
    const int arow = r0 + (l & 7) + (m & 1) * 8;   // A: m0/m2 rows 0-7, m1/m3 8-15
    const int aoff = (arow * SCH_STRIDE + (m >> 1) * 8) * 2;   // + kk*32
    const int brow = c0 + (m >> 1) * 8 + (l & 7);  // B: m0/m1 nt0, m2/m3 nt1
    const int bloff  = (brow * SCH_STRIDE + (m & 1) * 8) * 2;  // + kk*32
    const int bhioff = (brow * SBHI_STRIDE + (m & 1) * 8) * 2; // + gk*2

    const uint32_t sBhiU  = smem_u32(sBhi);
    const uint32_t bufU[2] = { smem_u32(sBuf0), smem_u32(sBuf1) };

    for (int t = 0; t < kT; ++t) {
        float acc[2][4];
#pragma unroll
        for (int nt = 0; nt < 2; ++nt) {
            acc[nt][0] = biasv[2 * nt];
            acc[nt][1] = biasv[2 * nt + 1];
            acc[nt][2] = biasv[2 * nt];
            acc[nt][3] = biasv[2 * nt + 1];
        }

        const int cstart = (t == 0) ? 8 : 0;   // h_{-1} == 0: only x chunk
        const int prevBuf = (t + 1) & 1;       // == (t-1)&1

        // ---- chunk loader (lambda): stage chunk c into buf ----
        auto load_chunk = [&](int c, uint32_t bu) {
            // A: 2 planes x 32 rows x 16 segs = 1024 segs
#pragma unroll
            for (int jj = 0; jj < 4; ++jj) {
                int idx   = tid + jj * 256;
                int plane = idx >> 9;
                int rem   = idx & 511;
                int row   = rem >> 4, seg = rem & 15;
                uint32_t dst = bu + plane * A_BYTES
                             + (row * SCH_STRIDE + seg * 8) * 2;
                const __nv_bfloat16* src;
                if (c < 8)
                    src = &g_h[prevBuf][plane]
                              [(size_t)(b0 + row) * kH + c * kChunk + seg * 8];
                else
                    src = &g_xs[plane]
                               [((size_t)(b0 + row) * kT + t) * kI + seg * 8];
                cpa16(dst, src);
            }
            // B_lo: 64 rows x 16 segs = 1024 segs
#pragma unroll
            for (int jj = 0; jj < 4; ++jj) {
                int idx = tid + jj * 256;
                int row = idx >> 4, seg = idx & 15;
                uint32_t dst = bu + 2 * A_BYTES
                             + (row * SCH_STRIDE + seg * 8) * 2;
                cpa16(dst, &g_W[1][(size_t)(j0 + row) * kK
                                   + c * kChunk + seg * 8]);
            }
        };

        load_chunk(cstart, bufU[cstart & 1]);
        cp_commit();

#pragma unroll 1
        for (int c = cstart; c <= 8; ++c) {
            if (c < 8) {
                load_chunk(c + 1, bufU[(c + 1) & 1]);
                cp_commit();
                cp_wait1();          // chunk c landed; c+1 in flight
            } else {
                cp_wait0();
            }
            __syncthreads();

            const uint32_t bu = bufU[c & 1];
            const uint32_t aHiB = bu + aoff;
            const uint32_t aLoB = bu + A_BYTES + aoff;
            const uint32_t bLoB = bu + 2 * A_BYTES + bloff;
            const uint32_t bHiB = sBhiU + bhioff + (c * kChunk) * 2;

#pragma unroll
            for (int kk = 0; kk < 8; ++kk) {
                uint32_t Ah[4], Al[4], Bh[4], Bl[4];
                ldm4(Ah, aHiB + kk * 32);
                ldm4(Al, aLoB + kk * 32);
                ldm4(Bh, bHiB + kk * 32);
                ldm4(Bl, bLoB + kk * 32);
                mma16816(acc[0], Ah, Bh[0], Bh[1]);
                mma16816(acc[1], Ah, Bh[2], Bh[3]);
                mma16816(acc[0], Ah, Bl[0], Bl[1]);
                mma16816(acc[1], Ah, Bl[2], Bl[3]);
                mma16816(acc[0], Al, Bh[0], Bh[1]);
                mma16816(acc[1], Al, Bh[2], Bh[3]);
            }
            __syncthreads();   // protect buf before it is refilled
        }

        // ---- epilogue: relu, write fp32 hid + bf16 hi/lo ping-pong ----
        const int curBuf = t & 1;
        const int rowA   = b0 + r0 + (l >> 2);
#pragma unroll
        for (int nt = 0; nt < 2; ++nt) {
            const int col = j0 + c0 + nt * 8 + 2 * (l & 3);
#pragma unroll
            for (int half = 0; half < 2; ++half) {
                float v0 = fmaxf(acc[nt][2 * half + 0], 0.0f);
                float v1 = fmaxf(acc[nt][2 * half + 1], 0.0f);
                const int row = rowA + half * 8;
                const size_t o = ((size_t)row * kT + t) * kH + col;
                float2 fv; fv.x = v0; fv.y = v1;
                *reinterpret_cast<float2*>(hid + o) = fv;

                __nv_bfloat16 h0, l0, h1, l1;
                split_bf16(v0, h0, l0);
                split_bf16(v1, h1, l1);
                __nv_bfloat162 ph; ph.x = h0; ph.y = h1;
                __nv_bfloat162 pl; pl.x = l0; pl.y = l1;
                const size_t ho = (size_t)row * kH + col;
                *reinterpret_cast<__nv_bfloat162*>(&g_h[curBuf][0][ho]) = ph;
                *reinterpret_cast<__nv_bfloat162*>(&g_h[curBuf][1][ho]) = pl;
            }
        }

        // ---- group barrier ----
        __threadfence();
        __syncthreads();
        if (tid == 0) {
            atomicAdd(&g_count[g], 1u);
            const unsigned int target =
                (unsigned int)(kTilesPerGroup * (t + 1));
            while (atomicAdd(&g_count[g], 0u) < target) { }
        }
        __syncthreads();
    }
}

// ---------------------------------------------------------------------------
// Output projection + softmax (unchanged fp32 path, ~1.1 ms):
//   outs[row] = softmax( hid[row] @ W_out^T + b_out )
// ---------------------------------------------------------------------------
__global__ __launch_bounds__(256, 1)
void rnn_output_kernel(const float* __restrict__ hid,
                       const float* __restrict__ W_out,
                       const float* __restrict__ b_out,
                       float* __restrict__ outs)
{
    __shared__ __align__(16) float Hs[32][68];
    __shared__ __align__(16) float Ws[32][132];

    const int tid = threadIdx.x;
    const int ty  = tid >> 4;
    const int tx  = tid & 15;
    const size_t r0 = (size_t)blockIdx.x * 64;

    float bias[8];
#pragma unroll
    for (int c = 0; c < 8; ++c) bias[c] = b_out[8 * tx + c];

    float acc[4][8];
#pragma unroll
    for (int i = 0; i < 4; ++i)
#pragma unroll
        for (int c = 0; c < 8; ++c) acc[i][c] = bias[c];

#pragma unroll 1
    for (int kt = 0; kt < 32; ++kt) {
        const int k0 = kt * 32;
        __syncthreads();
#pragma unroll
        for (int q = 0; q < 2; ++q) {
            int slot = tid + q * 256;
            int row  = slot >> 3;
            int kk4  = (slot & 7) * 4;
            float4 v = *reinterpret_cast<const float4*>(
                hid + (r0 + row) * kH + k0 + kk4);
            Hs[kk4 + 0][row] = v.x; Hs[kk4 + 1][row] = v.y;
            Hs[kk4 + 2][row] = v.z; Hs[kk4 + 3][row] = v.w;
        }
#pragma unroll
        for (int q = 0; q < 4; ++q) {
            int slot = tid + q * 256;
            int o    = slot >> 3;
            int kk4  = (slot & 7) * 4;
            float4 v = *reinterpret_cast<const float4*>(
                W_out + (size_t)o * kH + k0 + kk4);
            Ws[kk4 + 0][o] = v.x; Ws[kk4 + 1][o] = v.y;
            Ws[kk4 + 2][o] = v.z; Ws[kk4 + 3][o] = v.w;
        }
        __syncthreads();

#pragma unroll
        for (int kk = 0; kk < 32; ++kk) {
            float4 a  = *reinterpret_cast<const float4*>(&Hs[kk][4 * ty]);
            float4 w0 = *reinterpret_cast<const float4*>(&Ws[kk][8 * tx]);
            float4 w1 = *reinterpret_cast<const float4*>(&Ws[kk][8 * tx + 4]);
            float av[4] = {a.x, a.y, a.z, a.w};
            float wv[8] = {w0.x, w0.y, w0.z, w0.w, w1.x, w1.y, w1.z, w1.w};
#pragma unroll
            for (int i = 0; i < 4; ++i)
#pragma unroll
                for (int c = 0; c < 8; ++c)
                    acc[i][c] = fmaf(av[i], wv[c], acc[i][c]);
        }
    }

#pragma unroll
    for (int i = 0; i < 4; ++i) {
        float mx = acc[i][0];
#pragma unroll
        for (int c = 1; c < 8; ++c) mx = fmaxf(mx, acc[i][c]);
#pragma unroll
        for (int d = 8; d >= 1; d >>= 1)
            mx = fmaxf(mx, __shfl_xor_sync(0xffffffffu, mx, d, 16));

        float e[8], s = 0.0f;
#pragma unroll
        for (int c = 0; c < 8; ++c) { e[c] = expf(acc[i][c] - mx); s += e[c]; }
#pragma unroll
        for (int d = 8; d >= 1; d >>= 1)
            s += __shfl_xor_sync(0xffffffffu, s, d, 16);

        const float inv = 1.0f / s;
        const size_t row = r0 + 4 * ty + i;
        float4 o0, o1;
        o0.x = e[0] * inv; o0.y = e[1] * inv; o0.z = e[2] * inv; o0.w = e[3] * inv;
        o1.x = e[4] * inv; o1.y = e[5] * inv; o1.z = e[6] * inv; o1.w = e[7] * inv;
        *reinterpret_cast<float4*>(outs + row * kO + 8 * tx)     = o0;
        *reinterpret_cast<float4*>(outs + row * kO + 8 * tx + 4) = o1;
    }
}

// ---------------------------------------------------------------------------
// d_in order: x, W_in, b_in, Wrec, W_out, b_out
// d_out: hiddens [B,T,H] fp32 followed by outs [B,T,O] fp32
// ---------------------------------------------------------------------------
extern "C" void kernel_launch(void* const* d_in, const int* in_sizes, int n_in,
                              void* d_out, int out_size) {
    (void)in_sizes; (void)n_in; (void)out_size;
    const float* x     = (const float*)d_in[0];
    const float* W_in  = (const float*)d_in[1];
    const float* b_in  = (const float*)d_in[2];
    const float* Wrec  = (const float*)d_in[3];
    const float* W_out = (const float*)d_in[4];
    const float* b_out = (const float*)d_in[5];

    float* hid  = (float*)d_out;                 // [B,T,H]
    float* outs = hid + (size_t)kB * kT * kH;    // [B,T,O]

    cudaFuncSetAttribute(rnn_rec_tc,
                         cudaFuncAttributeMaxDynamicSharedMemorySize,
                         SMEM_TOTAL);

    convert_w_kernel<<<1152, 256>>>(Wrec, W_in);     // also resets counters
    convert_x_kernel<<<8192, 256>>>(x);
    rnn_rec_tc<<<kGroups * kTilesPerGroup, 256, SMEM_TOTAL>>>(b_in, hid);
    rnn_output_kernel<<<(kB * kT) / 64, 256>>>(hid, W_out, b_out, outs);
}

// round 6
// speedup vs baseline: 2.7024x; 1.0000x over previous
#include <cuda_runtime.h>
#include <cuda_bf16.h>
#include <math.h>
#include <stdint.h>

// Problem constants (nondecayRNN: B=256, T=512, I=128, H=1024, O=128)
namespace {
constexpr int kB = 256;
constexpr int kT = 512;
constexpr int kI = 128;
constexpr int kH = 1024;
constexpr int kO = 128;

constexpr int kGroups        = 8;                 // independent batch groups
constexpr int kBc            = kB / kGroups;      // 32 batch rows / group
constexpr int kTilesPerGroup = 16;                // N-tiles of 64 over H
constexpr int kTN            = kH / kTilesPerGroup; // 64

constexpr int kK      = kH + kI;   // fused K = 1152 (h | x)
constexpr int kChunk  = 128;       // K chunk per stage
// chunks 0..7 come from h (K=1024), chunk 8 from x (K=128)

// SMEM layout (bytes)
constexpr int SBHI_STRIDE = 1160;  // bf16 elems per n-row, padded (1152+8)
constexpr int SCH_STRIDE  = 136;   // bf16 elems per row in chunk bufs (128+8)
constexpr int A_BYTES   = 32 * SCH_STRIDE * 2;        // 8704
constexpr int BLO_BYTES = 64 * SCH_STRIDE * 2;        // 17408
constexpr int BUF_BYTES = 2 * A_BYTES + BLO_BYTES;    // 34816 (Ahi|Alo|Blo)
constexpr int BHI_BYTES = 64 * SBHI_STRIDE * 2;       // 148480 persistent
constexpr int SMEM_TOTAL = BHI_BYTES + 2 * BUF_BYTES; // 218112
}

// ---------------------------------------------------------------------------
// Device scratch (static __device__ arrays — no allocation)
// ---------------------------------------------------------------------------
__device__ unsigned int   g_count[kGroups];                 // group barriers
__device__ __nv_bfloat16  g_W[2][kH * kK];                  // [hi/lo][j*1152+k]
__device__ __nv_bfloat16  g_xs[2][(size_t)kB * kT * kI];    // [hi/lo][(b*T+t)*I+i]
__device__ __nv_bfloat16  g_h[2][2][(size_t)kB * kH];       // [buf][hi/lo][b*H+h]

// ---------------------------------------------------------------------------
// PTX helpers
// ---------------------------------------------------------------------------
__device__ __forceinline__ uint32_t smem_u32(const void* p) {
    return (uint32_t)__cvta_generic_to_shared(p);
}
__device__ __forceinline__ void cpa16(uint32_t dst, const void* src) {
    asm volatile("cp.async.cg.shared.global [%0], [%1], 16;"
                 :: "r"(dst), "l"(src) : "memory");
}
__device__ __forceinline__ void cp_commit() {
    asm volatile("cp.async.commit_group;" ::: "memory");
}
__device__ __forceinline__ void cp_wait0() {
    asm volatile("cp.async.wait_group 0;" ::: "memory");
}
__device__ __forceinline__ void cp_wait1() {
    asm volatile("cp.async.wait_group 1;" ::: "memory");
}
__device__ __forceinline__ void ldm4(uint32_t* r, uint32_t addr) {
    asm volatile("ldmatrix.sync.aligned.m8n8.x4.shared.b16 {%0,%1,%2,%3}, [%4];"
                 : "=r"(r[0]), "=r"(r[1]), "=r"(r[2]), "=r"(r[3]) : "r"(addr));
}
__device__ __forceinline__ void mma16816(float* d, const uint32_t* a,
                                         uint32_t b0, uint32_t b1) {
    asm volatile(
        "mma.sync.aligned.m16n8k16.row.col.f32.bf16.bf16.f32 "
        "{%0,%1,%2,%3}, {%4,%5,%6,%7}, {%8,%9}, {%0,%1,%2,%3};"
        : "+f"(d[0]), "+f"(d[1]), "+f"(d[2]), "+f"(d[3])
        : "r"(a[0]), "r"(a[1]), "r"(a[2]), "r"(a[3]), "r"(b0), "r"(b1));
}
__device__ __forceinline__ void split_bf16(float v, __nv_bfloat16& hi,
                                           __nv_bfloat16& lo) {
    hi = __float2bfloat16(v);
    lo = __float2bfloat16(v - __bfloat162float(hi));
}

// ---------------------------------------------------------------------------
// Prepass: split weights (Wrec|W_in concatenated along K) into bf16 hi/lo
// planes; also reset barrier counters.
// ---------------------------------------------------------------------------
__global__ void convert_w_kernel(const float* __restrict__ Wrec,
                                 const float* __restrict__ W_in) {
    if (blockIdx.x == 0 && threadIdx.x < kGroups) g_count[threadIdx.x] = 0u;
    const int total = kH * kK;
    for (int idx = blockIdx.x * blockDim.x + threadIdx.x; idx < total;
         idx += gridDim.x * blockDim.x) {
        int j = idx / kK, k = idx - j * kK;
        float v = (k < kH) ? Wrec[j * kH + k] : W_in[j * kI + (k - kH)];
        __nv_bfloat16 hi, lo;
        split_bf16(v, hi, lo);
        g_W[0][idx] = hi;
        g_W[1][idx] = lo;
    }
}

// Prepass: split x into bf16 hi/lo planes (same [B][T][I] layout).
__global__ void convert_x_kernel(const float* __restrict__ x) {
    const int n4 = (kB * kT * kI) / 4;
    __nv_bfloat162* xh = reinterpret_cast<__nv_bfloat162*>(g_xs[0]);
    __nv_bfloat162* xl = reinterpret_cast<__nv_bfloat162*>(g_xs[1]);
    for (int i = blockIdx.x * blockDim.x + threadIdx.x; i < n4;
         i += gridDim.x * blockDim.x) {
        float4 v = reinterpret_cast<const float4*>(x)[i];
        float vs[4] = {v.x, v.y, v.z, v.w};
        __nv_bfloat16 hi[4], lo[4];
#pragma unroll
        for (int k = 0; k < 4; ++k) split_bf16(vs[k], hi[k], lo[k]);
        __nv_bfloat162 p;
        p.x = hi[0]; p.y = hi[1]; xh[2 * i]     = p;
        p.x = hi[2]; p.y = hi[3]; xh[2 * i + 1] = p;
        p.x = lo[0]; p.y = lo[1]; xl[2 * i]     = p;
        p.x = lo[2]; p.y = lo[3]; xl[2 * i + 1] = p;
    }
}

// ---------------------------------------------------------------------------
// Tensor-core recurrence. Grid: 128 CTAs = 8 groups x 16 N-tiles.
// Block: 256 threads (8 warps; warp w -> rows 16*(w>>2), cols 16*(w&3)).
// Per CTA per step: 32(batch) x 64(H) output tile, K=1152 fused GEMM with the
// 3-pass bf16 split: D += Ah*Bh + Ah*Bl + Al*Bh. W_hi slice is SMEM-resident;
// W_lo and A(h/x hi+lo) are streamed per 128-wide K chunk via cp.async with
// double buffering.
// ---------------------------------------------------------------------------
__global__ __launch_bounds__(256, 1)
void rnn_rec_tc(const float* __restrict__ b_in,
                float* __restrict__ hid)   // [B, T, H] fp32 output
{
    extern __shared__ char smem[];
    char* sBhi  = smem;                    // persistent W_hi slice [64][1160]
    char* sBuf0 = smem + BHI_BYTES;        // chunk buf 0
    char* sBuf1 = sBuf0 + BUF_BYTES;       // chunk buf 1

    const int tid = threadIdx.x;
    const int g   = blockIdx.x / kTilesPerGroup;
    const int jt  = blockIdx.x % kTilesPerGroup;
    const int j0  = jt * kTN;
    const int b0  = g * kBc;
    const int w   = tid >> 5;
    const int l   = tid & 31;
    const int r0  = (w >> 2) * 16;   // A-row base within 32-row tile
    const int c0  = (w & 3) * 16;    // n base within 64-col tile

    // ---- persistent W_hi slice load (cp.async) ----
#pragma unroll
    for (int j = 0; j < 36; ++j) {                 // 9216 = 64 rows * 144 segs
        int idx = tid + j * 256;
        int row = idx / 144, seg = idx - row * 144;
        uint32_t dst = smem_u32(sBhi + (row * SBHI_STRIDE + seg * 8) * 2);
        cpa16(dst, &g_W[0][(size_t)(j0 + row) * kK + seg * 8]);
    }
    cp_commit();

    // bias per lane: cols nt*8 + 2*(l&3), +1
    float biasv[4];
#pragma unroll
    for (int nt = 0; nt < 2; ++nt) {
        int col = j0 + c0 + nt * 8 + 2 * (l & 3);
        biasv[2 * nt]     = b_in[col];
        biasv[2 * nt + 1] = b_in[col + 1];
    }

    cp_wait0();
    __syncthreads();

    // per-lane ldmatrix offsets
    const int m    = l >> 3;                       // matrix index 0..3
    const int arow = r0 + (l & 7) + (m & 1) * 8;   // A: m0/m2 rows 0-7, m1/m3 8-15
    const int aoff = (arow * SCH_STRIDE + (m >> 1) * 8) * 2;   // + kk*32
    const int brow = c0 + (m >> 1) * 8 + (l & 7);  // B: m0/m1 nt0, m2/m3 nt1
    const int bloff  = (brow * SCH_STRIDE + (m & 1) * 8) * 2;  // + kk*32
    const int bhioff = (brow * SBHI_STRIDE + (m & 1) * 8) * 2; // + gk*2

    const uint32_t sBhiU  = smem_u32(sBhi);
    const uint32_t bufU[2] = { smem_u32(sBuf0), smem_u32(sBuf1) };

    for (int t = 0; t < kT; ++t) {
        float acc[2][4];
#pragma unroll
        for (int nt = 0; nt < 2; ++nt) {
            acc[nt][0] = biasv[2 * nt];
            acc[nt][1] = biasv[2 * nt + 1];
            acc[nt][2] = biasv[2 * nt];
            acc[nt][3] = biasv[2 * nt + 1];
        }

        const int cstart = (t == 0) ? 8 : 0;   // h_{-1} == 0: only x chunk
        const int prevBuf = (t + 1) & 1;       // == (t-1)&1

        // ---- chunk loader (lambda): stage chunk c into buf ----
        auto load_chunk = [&](int c, uint32_t bu) {
            // A: 2 planes x 32 rows x 16 segs = 1024 segs
#pragma unroll
            for (int jj = 0; jj < 4; ++jj) {
                int idx   = tid + jj * 256;
                int plane = idx >> 9;
                int rem   = idx & 511;
                int row   = rem >> 4, seg = rem & 15;
                uint32_t dst = bu + plane * A_BYTES
                             + (row * SCH_STRIDE + seg * 8) * 2;
                const __nv_bfloat16* src;
                if (c < 8)
                    src = &g_h[prevBuf][plane]
                              [(size_t)(b0 + row) * kH + c * kChunk + seg * 8];
                else
                    src = &g_xs[plane]
                               [((size_t)(b0 + row) * kT + t) * kI + seg * 8];
                cpa16(dst, src);
            }
            // B_lo: 64 rows x 16 segs = 1024 segs
#pragma unroll
            for (int jj = 0; jj < 4; ++jj) {
                int idx = tid + jj * 256;
                int row = idx >> 4, seg = idx & 15;
                uint32_t dst = bu + 2 * A_BYTES
                             + (row * SCH_STRIDE + seg * 8) * 2;
                cpa16(dst, &g_W[1][(size_t)(j0 + row) * kK
                                   + c * kChunk + seg * 8]);
            }
        };

        load_chunk(cstart, bufU[cstart & 1]);
        cp_commit();

#pragma unroll 1
        for (int c = cstart; c <= 8; ++c) {
            if (c < 8) {
                load_chunk(c + 1, bufU[(c + 1) & 1]);
                cp_commit();
                cp_wait1();          // chunk c landed; c+1 in flight
            } else {
                cp_wait0();
            }
            __syncthreads();

            const uint32_t bu = bufU[c & 1];
            const uint32_t aHiB = bu + aoff;
            const uint32_t aLoB = bu + A_BYTES + aoff;
            const uint32_t bLoB = bu + 2 * A_BYTES + bloff;
            const uint32_t bHiB = sBhiU + bhioff + (c * kChunk) * 2;

#pragma unroll
            for (int kk = 0; kk < 8; ++kk) {
                uint32_t Ah[4], Al[4], Bh[4], Bl[4];
                ldm4(Ah, aHiB + kk * 32);
                ldm4(Al, aLoB + kk * 32);
                ldm4(Bh, bHiB + kk * 32);
                ldm4(Bl, bLoB + kk * 32);
                mma16816(acc[0], Ah, Bh[0], Bh[1]);
                mma16816(acc[1], Ah, Bh[2], Bh[3]);
                mma16816(acc[0], Ah, Bl[0], Bl[1]);
                mma16816(acc[1], Ah, Bl[2], Bl[3]);
                mma16816(acc[0], Al, Bh[0], Bh[1]);
                mma16816(acc[1], Al, Bh[2], Bh[3]);
            }
            __syncthreads();   // protect buf before it is refilled
        }

        // ---- epilogue: relu, write fp32 hid + bf16 hi/lo ping-pong ----
        const int curBuf = t & 1;
        const int rowA   = b0 + r0 + (l >> 2);
#pragma unroll
        for (int nt = 0; nt < 2; ++nt) {
            const int col = j0 + c0 + nt * 8 + 2 * (l & 3);
#pragma unroll
            for (int half = 0; half < 2; ++half) {
                float v0 = fmaxf(acc[nt][2 * half + 0], 0.0f);
                float v1 = fmaxf(acc[nt][2 * half + 1], 0.0f);
                const int row = rowA + half * 8;
                const size_t o = ((size_t)row * kT + t) * kH + col;
                float2 fv; fv.x = v0; fv.y = v1;
                *reinterpret_cast<float2*>(hid + o) = fv;

                __nv_bfloat16 h0, l0, h1, l1;
                split_bf16(v0, h0, l0);
                split_bf16(v1, h1, l1);
                __nv_bfloat162 ph; ph.x = h0; ph.y = h1;
                __nv_bfloat162 pl; pl.x = l0; pl.y = l1;
                const size_t ho = (size_t)row * kH + col;
                *reinterpret_cast<__nv_bfloat162*>(&g_h[curBuf][0][ho]) = ph;
                *reinterpret_cast<__nv_bfloat162*>(&g_h[curBuf][1][ho]) = pl;
            }
        }

        // ---- group barrier ----
        __threadfence();
        __syncthreads();
        if (tid == 0) {
            atomicAdd(&g_count[g], 1u);
            const unsigned int target =
                (unsigned int)(kTilesPerGroup * (t + 1));
            while (atomicAdd(&g_count[g], 0u) < target) { }
        }
        __syncthreads();
    }
}

// ---------------------------------------------------------------------------
// Output projection + softmax (unchanged fp32 path, ~1.1 ms):
//   outs[row] = softmax( hid[row] @ W_out^T + b_out )
// ---------------------------------------------------------------------------
__global__ __launch_bounds__(256, 1)
void rnn_output_kernel(const float* __restrict__ hid,
                       const float* __restrict__ W_out,
                       const float* __restrict__ b_out,
                       float* __restrict__ outs)
{
    __shared__ __align__(16) float Hs[32][68];
    __shared__ __align__(16) float Ws[32][132];

    const int tid = threadIdx.x;
    const int ty  = tid >> 4;
    const int tx  = tid & 15;
    const size_t r0 = (size_t)blockIdx.x * 64;

    float bias[8];
#pragma unroll
    for (int c = 0; c < 8; ++c) bias[c] = b_out[8 * tx + c];

    float acc[4][8];
#pragma unroll
    for (int i = 0; i < 4; ++i)
#pragma unroll
        for (int c = 0; c < 8; ++c) acc[i][c] = bias[c];

#pragma unroll 1
    for (int kt = 0; kt < 32; ++kt) {
        const int k0 = kt * 32;
        __syncthreads();
#pragma unroll
        for (int q = 0; q < 2; ++q) {
            int slot = tid + q * 256;
            int row  = slot >> 3;
            int kk4  = (slot & 7) * 4;
            float4 v = *reinterpret_cast<const float4*>(
                hid + (r0 + row) * kH + k0 + kk4);
            Hs[kk4 + 0][row] = v.x; Hs[kk4 + 1][row] = v.y;
            Hs[kk4 + 2][row] = v.z; Hs[kk4 + 3][row] = v.w;
        }
#pragma unroll
        for (int q = 0; q < 4; ++q) {
            int slot = tid + q * 256;
            int o    = slot >> 3;
            int kk4  = (slot & 7) * 4;
            float4 v = *reinterpret_cast<const float4*>(
                W_out + (size_t)o * kH + k0 + kk4);
            Ws[kk4 + 0][o] = v.x; Ws[kk4 + 1][o] = v.y;
            Ws[kk4 + 2][o] = v.z; Ws[kk4 + 3][o] = v.w;
        }
        __syncthreads();

#pragma unroll
        for (int kk = 0; kk < 32; ++kk) {
            float4 a  = *reinterpret_cast<const float4*>(&Hs[kk][4 * ty]);
            float4 w0 = *reinterpret_cast<const float4*>(&Ws[kk][8 * tx]);
            float4 w1 = *reinterpret_cast<const float4*>(&Ws[kk][8 * tx + 4]);
            float av[4] = {a.x, a.y, a.z, a.w};
            float wv[8] = {w0.x, w0.y, w0.z, w0.w, w1.x, w1.y, w1.z, w1.w};
#pragma unroll
            for (int i = 0; i < 4; ++i)
#pragma unroll
                for (int c = 0; c < 8; ++c)
                    acc[i][c] = fmaf(av[i], wv[c], acc[i][c]);
        }
    }

#pragma unroll
    for (int i = 0; i < 4; ++i) {
        float mx = acc[i][0];
#pragma unroll
        for (int c = 1; c < 8; ++c) mx = fmaxf(mx, acc[i][c]);
#pragma unroll
        for (int d = 8; d >= 1; d >>= 1)
            mx = fmaxf(mx, __shfl_xor_sync(0xffffffffu, mx, d, 16));

        float e[8], s = 0.0f;
#pragma unroll
        for (int c = 0; c < 8; ++c) { e[c] = expf(acc[i][c] - mx); s += e[c]; }
#pragma unroll
        for (int d = 8; d >= 1; d >>= 1)
            s += __shfl_xor_sync(0xffffffffu, s, d, 16);

        const float inv = 1.0f / s;
        const size_t row = r0 + 4 * ty + i;
        float4 o0, o1;
        o0.x = e[0] * inv; o0.y = e[1] * inv; o0.z = e[2] * inv; o0.w = e[3] * inv;
        o1.x = e[4] * inv; o1.y = e[5] * inv; o1.z = e[6] * inv; o1.w = e[7] * inv;
        *reinterpret_cast<float4*>(outs + row * kO + 8 * tx)     = o0;
        *reinterpret_cast<float4*>(outs + row * kO + 8 * tx + 4) = o1;
    }
}

// ---------------------------------------------------------------------------
// d_in order: x, W_in, b_in, Wrec, W_out, b_out
// d_out: hiddens [B,T,H] fp32 followed by outs [B,T,O] fp32
// ---------------------------------------------------------------------------
extern "C" void kernel_launch(void* const* d_in, const int* in_sizes, int n_in,
                              void* d_out, int out_size) {
    (void)in_sizes; (void)n_in; (void)out_size;
    const float* x     = (const float*)d_in[0];
    const float* W_in  = (const float*)d_in[1];
    const float* b_in  = (const float*)d_in[2];
    const float* Wrec  = (const float*)d_in[3];
    const float* W_out = (const float*)d_in[4];
    const float* b_out = (const float*)d_in[5];

    float* hid  = (float*)d_out;                 // [B,T,H]
    float* outs = hid + (size_t)kB * kT * kH;    // [B,T,O]

    cudaFuncSetAttribute(rnn_rec_tc,
                         cudaFuncAttributeMaxDynamicSharedMemorySize,
                         SMEM_TOTAL);

    convert_w_kernel<<<1152, 256>>>(Wrec, W_in);     // also resets counters
    convert_x_kernel<<<8192, 256>>>(x);
    rnn_rec_tc<<<kGroups * kTilesPerGroup, 256, SMEM_TOTAL>>>(b_in, hid);
    rnn_output_kernel<<<(kB * kT) / 64, 256>>>(hid, W_out, b_out, outs);
}

// round 7
// speedup vs baseline: 3.2942x; 1.2190x over previous
#include <cuda_runtime.h>
#include <cuda_bf16.h>
#include <math.h>
#include <stdint.h>

// Problem constants (nondecayRNN: B=256, T=512, I=128, H=1024, O=128)
namespace {
constexpr int kB = 256;
constexpr int kT = 512;
constexpr int kI = 128;
constexpr int kH = 1024;
constexpr int kO = 128;

constexpr int kGroups        = 8;                 // independent batch groups
constexpr int kBc            = kB / kGroups;      // 32 batch rows / group
constexpr int kTilesPerGroup = 16;                // N-tiles of 64 over H
constexpr int kTN            = kH / kTilesPerGroup; // 64

constexpr int kK      = kH + kI;   // fused K = 1152 (h | x)
constexpr int kChunk  = 128;       // K chunk per stage (h chunks 0..7, x = idx 8)

// Recurrence SMEM layout (bytes)
constexpr int SBHI_STRIDE = 1160;  // bf16 elems per n-row, padded (1152+8)
constexpr int SCH_STRIDE  = 136;   // bf16 elems per row in chunk bufs (128+8)
constexpr int A_BYTES   = 32 * SCH_STRIDE * 2;        // 8704
constexpr int BLO_BYTES = 64 * SCH_STRIDE * 2;        // 17408
constexpr int BUF_BYTES = 2 * A_BYTES + BLO_BYTES;    // 34816 (Ahi|Alo|Blo)
constexpr int BHI_BYTES = 64 * SBHI_STRIDE * 2;       // 148480 persistent
constexpr int SMEM_TOTAL = BHI_BYTES + 2 * BUF_BYTES; // 218112

// Output kernel config: CTA = 128 (b,t) rows x 128 O-cols, K=1024 in 16x64
constexpr int kORows  = 128;
constexpr int kOChunk = 64;
constexpr int OST     = 72;                 // padded chunk stride (elems)
constexpr int OPA     = kORows * OST * 2;   // 18432 B per plane tile
constexpr int OBUF    = 4 * OPA;            // Ahi|Alo|Bhi|Blo = 73728
constexpr int OSMEM   = 2 * OBUF;           // 147456
}

// ---------------------------------------------------------------------------
// Device scratch (static __device__ arrays — no runtime allocation)
// ---------------------------------------------------------------------------
__device__ unsigned int   g_count[kGroups];                 // group barriers
__device__ __nv_bfloat16  g_W[2][kH * kK];                  // [hi/lo][j*1152+k]
__device__ __nv_bfloat16  g_Wout[2][kO * kH];               // [hi/lo][o*1024+k]
__device__ __nv_bfloat16  g_xs[2][(size_t)kB * kT * kI];    // [hi/lo][(b*T+t)*I+i]
__device__ __nv_bfloat16  g_hb[2][(size_t)kB * kT * kH];    // [hi/lo][(b*T+t)*H+h]

// ---------------------------------------------------------------------------
// PTX helpers
// ---------------------------------------------------------------------------
__device__ __forceinline__ uint32_t smem_u32(const void* p) {
    return (uint32_t)__cvta_generic_to_shared(p);
}
__device__ __forceinline__ void cpa16(uint32_t dst, const void* src) {
    asm volatile("cp.async.cg.shared.global [%0], [%1], 16;"
                 :: "r"(dst), "l"(src) : "memory");
}
__device__ __forceinline__ void cp_commit() {
    asm volatile("cp.async.commit_group;" ::: "memory");
}
__device__ __forceinline__ void cp_wait0() {
    asm volatile("cp.async.wait_group 0;" ::: "memory");
}
__device__ __forceinline__ void cp_wait1() {
    asm volatile("cp.async.wait_group 1;" ::: "memory");
}
__device__ __forceinline__ void ldm4(uint32_t* r, uint32_t addr) {
    asm volatile("ldmatrix.sync.aligned.m8n8.x4.shared.b16 {%0,%1,%2,%3}, [%4];"
                 : "=r"(r[0]), "=r"(r[1]), "=r"(r[2]), "=r"(r[3]) : "r"(addr));
}
__device__ __forceinline__ void mma16816(float* d, const uint32_t* a,
                                         uint32_t b0, uint32_t b1) {
    asm volatile(
        "mma.sync.aligned.m16n8k16.row.col.f32.bf16.bf16.f32 "
        "{%0,%1,%2,%3}, {%4,%5,%6,%7}, {%8,%9}, {%0,%1,%2,%3};"
        : "+f"(d[0]), "+f"(d[1]), "+f"(d[2]), "+f"(d[3])
        : "r"(a[0]), "r"(a[1]), "r"(a[2]), "r"(a[3]), "r"(b0), "r"(b1));
}
__device__ __forceinline__ void split_bf16(float v, __nv_bfloat16& hi,
                                           __nv_bfloat16& lo) {
    hi = __float2bfloat16(v);
    lo = __float2bfloat16(v - __bfloat162float(hi));
}
__device__ __forceinline__ void barrier_arrive(unsigned int* p) {
    asm volatile("red.release.gpu.global.add.u32 [%0], %1;"
                 :: "l"(p), "r"(1u) : "memory");
}
__device__ __forceinline__ unsigned int ld_acquire(const unsigned int* p) {
    unsigned int v;
    asm volatile("ld.acquire.gpu.global.u32 %0, [%1];"
                 : "=r"(v) : "l"(p) : "memory");
    return v;
}

// ---------------------------------------------------------------------------
// Prepass: split Wrec|W_in (K-fused) and W_out into bf16 hi/lo planes;
// reset barrier counters (keeps kernel_launch graph-replay deterministic).
// ---------------------------------------------------------------------------
__global__ void convert_w_kernel(const float* __restrict__ Wrec,
                                 const float* __restrict__ W_in,
                                 const float* __restrict__ W_out) {
    if (blockIdx.x == 0 && threadIdx.x < kGroups) g_count[threadIdx.x] = 0u;
    const int totalW = kH * kK;
    for (int idx = blockIdx.x * blockDim.x + threadIdx.x; idx < totalW;
         idx += gridDim.x * blockDim.x) {
        int j = idx / kK, k = idx - j * kK;
        float v = (k < kH) ? Wrec[j * kH + k] : W_in[j * kI + (k - kH)];
        __nv_bfloat16 hi, lo;
        split_bf16(v, hi, lo);
        g_W[0][idx] = hi;
        g_W[1][idx] = lo;
    }
    const int totalO = kO * kH;
    for (int idx = blockIdx.x * blockDim.x + threadIdx.x; idx < totalO;
         idx += gridDim.x * blockDim.x) {
        __nv_bfloat16 hi, lo;
        split_bf16(W_out[idx], hi, lo);
        g_Wout[0][idx] = hi;
        g_Wout[1][idx] = lo;
    }
}

// Prepass: split x into bf16 hi/lo planes (same [B][T][I] layout).
__global__ void convert_x_kernel(const float* __restrict__ x) {
    const int n4 = (kB * kT * kI) / 4;
    __nv_bfloat162* xh = reinterpret_cast<__nv_bfloat162*>(g_xs[0]);
    __nv_bfloat162* xl = reinterpret_cast<__nv_bfloat162*>(g_xs[1]);
    for (int i = blockIdx.x * blockDim.x + threadIdx.x; i < n4;
         i += gridDim.x * blockDim.x) {
        float4 v = reinterpret_cast<const float4*>(x)[i];
        float vs[4] = {v.x, v.y, v.z, v.w};
        __nv_bfloat16 hi[4], lo[4];
#pragma unroll
        for (int k = 0; k < 4; ++k) split_bf16(vs[k], hi[k], lo[k]);
        __nv_bfloat162 p;
        p.x = hi[0]; p.y = hi[1]; xh[2 * i]     = p;
        p.x = hi[2]; p.y = hi[3]; xh[2 * i + 1] = p;
        p.x = lo[0]; p.y = lo[1]; xl[2 * i]     = p;
        p.x = lo[2]; p.y = lo[3]; xl[2 * i + 1] = p;
    }
}

// ---------------------------------------------------------------------------
// Tensor-core recurrence. Grid: 128 CTAs = 8 groups x 16 N-tiles, 256 thr.
// Step order per t:  x-chunk (independent of h_{t-1}, hides barrier skew)
//   -> acquire-wait group barrier -> 8 h-chunks (2-buffer cp.async pipeline)
//   -> relu epilogue (fp32 hid + bf16 hi/lo planes) -> release-arrive.
// 3-pass bf16 split: D += Ah*Bh + Ah*Bl + Al*Bh. W_hi slice SMEM-persistent.
// ---------------------------------------------------------------------------
__global__ __launch_bounds__(256, 1)
void rnn_rec_tc(const float* __restrict__ b_in,
                float* __restrict__ hid)   // [B, T, H] fp32 output
{
    extern __shared__ char smem[];
    char* sBhi  = smem;                    // persistent W_hi slice [64][1160]
    char* sBuf0 = smem + BHI_BYTES;
    char* sBuf1 = sBuf0 + BUF_BYTES;

    const int tid = threadIdx.x;
    const int g   = blockIdx.x / kTilesPerGroup;
    const int jt  = blockIdx.x % kTilesPerGroup;
    const int j0  = jt * kTN;
    const int b0  = g * kBc;
    const int w   = tid >> 5;
    const int l   = tid & 31;
    const int r0  = (w >> 2) * 16;   // A-row base within 32-row tile
    const int c0  = (w & 3) * 16;    // n base within 64-col tile

    // ---- persistent W_hi slice load (cp.async) ----
#pragma unroll
    for (int j = 0; j < 36; ++j) {                 // 9216 = 64 rows * 144 segs
        int idx = tid + j * 256;
        int row = idx / 144, seg = idx - row * 144;
        uint32_t dst = smem_u32(sBhi + (row * SBHI_STRIDE + seg * 8) * 2);
        cpa16(dst, &g_W[0][(size_t)(j0 + row) * kK + seg * 8]);
    }
    cp_commit();

    float biasv[4];
#pragma unroll
    for (int nt = 0; nt < 2; ++nt) {
        int col = j0 + c0 + nt * 8 + 2 * (l & 3);
        biasv[2 * nt]     = b_in[col];
        biasv[2 * nt + 1] = b_in[col + 1];
    }

    cp_wait0();
    __syncthreads();

    // per-lane ldmatrix offsets
    const int m    = l >> 3;
    const int arow = r0 + (l & 7) + (m & 1) * 8;
    const int aoff = (arow * SCH_STRIDE + (m >> 1) * 8) * 2;
    const int brow = c0 + (m >> 1) * 8 + (l & 7);
    const int bloff  = (brow * SCH_STRIDE + (m & 1) * 8) * 2;
    const int bhioff = (brow * SBHI_STRIDE + (m & 1) * 8) * 2;

    const uint32_t sBhiU   = smem_u32(sBhi);
    const uint32_t bufU[2] = { smem_u32(sBuf0), smem_u32(sBuf1) };

    for (int t = 0; t < kT; ++t) {
        float acc[2][4];
#pragma unroll
        for (int nt = 0; nt < 2; ++nt) {
            acc[nt][0] = biasv[2 * nt];
            acc[nt][1] = biasv[2 * nt + 1];
            acc[nt][2] = biasv[2 * nt];
            acc[nt][3] = biasv[2 * nt + 1];
        }

        // chunk loaders -------------------------------------------------
        auto load_x_chunk = [&](uint32_t bu) {
#pragma unroll
            for (int jj = 0; jj < 4; ++jj) {         // A: 2 planes x 32r x 16s
                int idx = tid + jj * 256;
                int plane = idx >> 9, rem = idx & 511;
                int row = rem >> 4, seg = rem & 15;
                cpa16(bu + plane * A_BYTES + (row * SCH_STRIDE + seg * 8) * 2,
                      &g_xs[plane][((size_t)(b0 + row) * kT + t) * kI + seg * 8]);
            }
#pragma unroll
            for (int jj = 0; jj < 4; ++jj) {         // B_lo: 64 x 16
                int idx = tid + jj * 256;
                int row = idx >> 4, seg = idx & 15;
                cpa16(bu + 2 * A_BYTES + (row * SCH_STRIDE + seg * 8) * 2,
                      &g_W[1][(size_t)(j0 + row) * kK + kH + seg * 8]);
            }
        };
        auto load_h_chunk = [&](int c, uint32_t bu) {
#pragma unroll
            for (int jj = 0; jj < 4; ++jj) {
                int idx = tid + jj * 256;
                int plane = idx >> 9, rem = idx & 511;
                int row = rem >> 4, seg = rem & 15;
                cpa16(bu + plane * A_BYTES + (row * SCH_STRIDE + seg * 8) * 2,
                      &g_hb[plane][((size_t)(b0 + row) * kT + (t - 1)) * kH
                                   + c * kChunk + seg * 8]);
            }
#pragma unroll
            for (int jj = 0; jj < 4; ++jj) {
                int idx = tid + jj * 256;
                int row = idx >> 4, seg = idx & 15;
                cpa16(bu + 2 * A_BYTES + (row * SCH_STRIDE + seg * 8) * 2,
                      &g_W[1][(size_t)(j0 + row) * kK + c * kChunk + seg * 8]);
            }
        };
        auto do_chunk_mma = [&](uint32_t bu, int kbase) {
            const uint32_t aHiB = bu + aoff;
            const uint32_t aLoB = bu + A_BYTES + aoff;
            const uint32_t bLoB = bu + 2 * A_BYTES + bloff;
            const uint32_t bHiB = sBhiU + bhioff + kbase * 2;
#pragma unroll
            for (int kk = 0; kk < 8; ++kk) {
                uint32_t Ah[4], Al[4], Bh[4], Bl[4];
                ldm4(Ah, aHiB + kk * 32);
                ldm4(Al, aLoB + kk * 32);
                ldm4(Bh, bHiB + kk * 32);
                ldm4(Bl, bLoB + kk * 32);
                mma16816(acc[0], Ah, Bh[0], Bh[1]);
                mma16816(acc[1], Ah, Bh[2], Bh[3]);
                mma16816(acc[0], Ah, Bl[0], Bl[1]);
                mma16816(acc[1], Ah, Bl[2], Bl[3]);
                mma16816(acc[0], Al, Bh[0], Bh[1]);
                mma16816(acc[1], Al, Bh[2], Bh[3]);
            }
        };

        // ---- phase 1: x chunk (no dependency on h_{t-1}) ----
        load_x_chunk(bufU[0]);
        cp_commit();
        cp_wait0();
        __syncthreads();
        do_chunk_mma(bufU[0], kH);
        __syncthreads();

        // ---- phase 2: wait for h_{t-1} (group barrier, acquire) ----
        if (t > 0) {
            if (tid == 0) {
                const unsigned int target =
                    (unsigned int)(kTilesPerGroup * t);
                while (ld_acquire(&g_count[g]) < target) { }
            }
            __syncthreads();

            // ---- phase 3: 8 h-chunks, 2-buffer pipeline ----
            load_h_chunk(0, bufU[0]);
            cp_commit();
#pragma unroll 1
            for (int c = 0; c < 8; ++c) {
                if (c < 7) {
                    load_h_chunk(c + 1, bufU[(c + 1) & 1]);
                    cp_commit();
                    cp_wait1();
                } else {
                    cp_wait0();
                }
                __syncthreads();
                do_chunk_mma(bufU[c & 1], c * kChunk);
                __syncthreads();
            }
        }

        // ---- epilogue: relu, fp32 hid + bf16 hi/lo planes ----
        const int rowA = b0 + r0 + (l >> 2);
#pragma unroll
        for (int nt = 0; nt < 2; ++nt) {
            const int col = j0 + c0 + nt * 8 + 2 * (l & 3);
#pragma unroll
            for (int half = 0; half < 2; ++half) {
                float v0 = fmaxf(acc[nt][2 * half + 0], 0.0f);
                float v1 = fmaxf(acc[nt][2 * half + 1], 0.0f);
                const int row = rowA + half * 8;
                const size_t o = ((size_t)row * kT + t) * kH + col;
                float2 fv; fv.x = v0; fv.y = v1;
                *reinterpret_cast<float2*>(hid + o) = fv;

                __nv_bfloat16 h0, l0, h1, l1;
                split_bf16(v0, h0, l0);
                split_bf16(v1, h1, l1);
                __nv_bfloat162 ph; ph.x = h0; ph.y = h1;
                __nv_bfloat162 pl; pl.x = l0; pl.y = l1;
                *reinterpret_cast<__nv_bfloat162*>(&g_hb[0][o]) = ph;
                *reinterpret_cast<__nv_bfloat162*>(&g_hb[1][o]) = pl;
            }
        }

        // ---- arrive (release). Next iteration's x phase hides the skew.
        __syncthreads();
        if (tid == 0) barrier_arrive(&g_count[g]);
    }
}

// ---------------------------------------------------------------------------
// Tensorized output projection + softmax.
// Grid: 1024 CTAs x 256 thr. CTA = 128 (b,t) rows x 128 O-cols, K=1024 in
// 16 chunks of 64, 2-buffer cp.async. Warp w -> rows 16w..16w+15, all cols.
// Same 3-pass bf16 split; A read from g_hb planes written by the recurrence.
// ---------------------------------------------------------------------------
__global__ __launch_bounds__(256, 1)
void rnn_output_tc(const float* __restrict__ b_out,
                   float* __restrict__ outs)
{
    extern __shared__ char smem[];
    const int tid = threadIdx.x;
    const int w   = tid >> 5;
    const int l   = tid & 31;
    const int m   = l >> 3;
    const size_t r0g = (size_t)blockIdx.x * kORows;

    const int aoff = ((w * 16 + (l & 7) + (m & 1) * 8) * OST + (m >> 1) * 8) * 2;
    const int boff = (((m >> 1) * 8 + (l & 7)) * OST + (m & 1) * 8) * 2;
    const uint32_t bufU[2] = { smem_u32(smem), smem_u32(smem + OBUF) };

    float acc[16][4];
#pragma unroll
    for (int j = 0; j < 16; ++j) {
        const int col = j * 8 + 2 * (l & 3);
        float bv0 = b_out[col], bv1 = b_out[col + 1];
        acc[j][0] = bv0; acc[j][1] = bv1; acc[j][2] = bv0; acc[j][3] = bv1;
    }

    auto load_chunk = [&](int c, uint32_t bu) {
        const int k0 = c * kOChunk;
#pragma unroll
        for (int jj = 0; jj < 8; ++jj) {     // A: 2 planes x 128 rows x 8 segs
            int idx = tid + jj * 256;
            int plane = idx >> 10, rem = idx & 1023;
            int row = rem >> 3, seg = rem & 7;
            cpa16(bu + plane * OPA + (row * OST + seg * 8) * 2,
                  &g_hb[plane][(r0g + row) * kH + k0 + seg * 8]);
        }
#pragma unroll
        for (int jj = 0; jj < 8; ++jj) {     // B: 2 planes x 128 n x 8 segs
            int idx = tid + jj * 256;
            int plane = idx >> 10, rem = idx & 1023;
            int row = rem >> 3, seg = rem & 7;
            cpa16(bu + 2 * OPA + plane * OPA + (row * OST + seg * 8) * 2,
                  &g_Wout[plane][(size_t)row * kH + k0 + seg * 8]);
        }
    };

    load_chunk(0, bufU[0]);
    cp_commit();

#pragma unroll 1
    for (int c = 0; c < 16; ++c) {
        if (c < 15) {
            load_chunk(c + 1, bufU[(c + 1) & 1]);
            cp_commit();
            cp_wait1();
        } else {
            cp_wait0();
        }
        __syncthreads();

        const uint32_t bu  = bufU[c & 1];
        const uint32_t aHi = bu + aoff;
        const uint32_t aLo = bu + OPA + aoff;
        const uint32_t bHi = bu + 2 * OPA + boff;
        const uint32_t bLo = bu + 3 * OPA + boff;

#pragma unroll
        for (int kk = 0; kk < 4; ++kk) {
            uint32_t Ah[4], Al[4];
            ldm4(Ah, aHi + kk * 32);
            ldm4(Al, aLo + kk * 32);
#pragma unroll
            for (int nf = 0; nf < 8; ++nf) {
                uint32_t Bh[4], Bl[4];
                ldm4(Bh, bHi + nf * (16 * OST * 2) + kk * 32);
                ldm4(Bl, bLo + nf * (16 * OST * 2) + kk * 32);
                mma16816(acc[2 * nf],     Ah, Bh[0], Bh[1]);
                mma16816(acc[2 * nf + 1], Ah, Bh[2], Bh[3]);
                mma16816(acc[2 * nf],     Ah, Bl[0], Bl[1]);
                mma16816(acc[2 * nf + 1], Ah, Bl[2], Bl[3]);
                mma16816(acc[2 * nf],     Al, Bh[0], Bh[1]);
                mma16816(acc[2 * nf + 1], Al, Bh[2], Bh[3]);
            }
        }
        __syncthreads();
    }

    // softmax: lane holds 32 logits of row (l>>2) [vals 0,1] and of row
    // (l>>2)+8 [vals 2,3]; full row lives in the 4 lanes sharing l>>2.
#pragma unroll
    for (int half = 0; half < 2; ++half) {
        float mx = -1e30f;
#pragma unroll
        for (int j = 0; j < 16; ++j) {
            mx = fmaxf(mx, acc[j][2 * half + 0]);
            mx = fmaxf(mx, acc[j][2 * half + 1]);
        }
        mx = fmaxf(mx, __shfl_xor_sync(0xffffffffu, mx, 1));
        mx = fmaxf(mx, __shfl_xor_sync(0xffffffffu, mx, 2));

        float e[32], s = 0.0f;
#pragma unroll
        for (int j = 0; j < 16; ++j) {
            e[2 * j]     = expf(acc[j][2 * half + 0] - mx);
            e[2 * j + 1] = expf(acc[j][2 * half + 1] - mx);
            s += e[2 * j] + e[2 * j + 1];
        }
        s += __shfl_xor_sync(0xffffffffu, s, 1);
        s += __shfl_xor_sync(0xffffffffu, s, 2);
        const float inv = 1.0f / s;

        const size_t row = r0g + w * 16 + (l >> 2) + half * 8;
#pragma unroll
        for (int j = 0; j < 16; ++j) {
            float2 o;
            o.x = e[2 * j] * inv;
            o.y = e[2 * j + 1] * inv;
            *reinterpret_cast<float2*>(
                outs + row * kO + j * 8 + 2 * (l & 3)) = o;
        }
    }
}

// ---------------------------------------------------------------------------
// d_in order: x, W_in, b_in, Wrec, W_out, b_out
// d_out: hiddens [B,T,H] fp32 followed by outs [B,T,O] fp32
// ---------------------------------------------------------------------------
extern "C" void kernel_launch(void* const* d_in, const int* in_sizes, int n_in,
                              void* d_out, int out_size) {
    (void)in_sizes; (void)n_in; (void)out_size;
    const float* x     = (const float*)d_in[0];
    const float* W_in  = (const float*)d_in[1];
    const float* b_in  = (const float*)d_in[2];
    const float* Wrec  = (const float*)d_in[3];
    const float* W_out = (const float*)d_in[4];
    const float* b_out = (const float*)d_in[5];

    float* hid  = (float*)d_out;                 // [B,T,H]
    float* outs = hid + (size_t)kB * kT * kH;    // [B,T,O]

    cudaFuncSetAttribute(rnn_rec_tc,
                         cudaFuncAttributeMaxDynamicSharedMemorySize,
                         SMEM_TOTAL);
    cudaFuncSetAttribute(rnn_output_tc,
                         cudaFuncAttributeMaxDynamicSharedMemorySize,
                         OSMEM);

    convert_w_kernel<<<1152, 256>>>(Wrec, W_in, W_out);   // also resets counters
    convert_x_kernel<<<8192, 256>>>(x);
    rnn_rec_tc<<<kGroups * kTilesPerGroup, 256, SMEM_TOTAL>>>(b_in, hid);
    rnn_output_tc<<<(kB * kT) / kORows, 256, OSMEM>>>(b_out, outs);
}